// round 8
// baseline (speedup 1.0000x reference)
#include <cuda_runtime.h>

typedef unsigned long long u64;

// ---- packed fp32x2 helpers (Blackwell FFMA2 path, PTX-only) ----
__device__ __forceinline__ u64 pack2(float lo, float hi) {
    u64 r;
    asm("mov.b64 %0, {%1, %2};" : "=l"(r) : "f"(lo), "f"(hi));
    return r;
}
__device__ __forceinline__ float2 unpack2(u64 v) {
    float2 f;
    asm("mov.b64 {%0, %1}, %2;" : "=f"(f.x), "=f"(f.y) : "l"(v));
    return f;
}
__device__ __forceinline__ void fma2(u64& d, u64 a, u64 b) {
    asm("fma.rn.f32x2 %0, %1, %2, %0;" : "+l"(d) : "l"(a), "l"(b));
}

// Scratch for x_mixed / v_mixed: [2*B, 1024] fp32 = 256 MiB (bss-style, no alloc)
__device__ float g_mixed[2u * 32768u * 1024u];

#define BPB 4  // batches per block in the attention kernel

// ---------------------------------------------------------------------------
// Kernel A: q/k projection + geodesic softmax + mixing, 4 batches per block.
// Dynamic smem layout (floats):
//   sWq[64*65] sWk[64*65] sX[BPB*1024] sV[BPB*1024]
//   sQ[BPB*16*65] sK[BPB*16*65] sA[BPB*16*17] sQs[BPB*16] sKs[BPB*16]
// ---------------------------------------------------------------------------
__global__ __launch_bounds__(256) void attn_mix_kernel(
    const float* __restrict__ x, const float* __restrict__ v,
    const float* __restrict__ Wq, const float* __restrict__ bq,
    const float* __restrict__ Wk, const float* __restrict__ bk,
    int B)
{
    extern __shared__ float sm[];
    float* sWq = sm;                     // 4160
    float* sWk = sWq + 64 * 65;          // 4160
    float* sX  = sWk + 64 * 65;          // 4096 (16B aligned: offset 8320 floats)
    float* sV  = sX  + BPB * 1024;       // 4096
    float* sQ  = sV  + BPB * 1024;       // 4160
    float* sK  = sQ  + BPB * 16 * 65;    // 4160
    float* sA  = sK  + BPB * 16 * 65;    // 1088
    float* sQs = sA  + BPB * 16 * 17;    // 64
    float* sKs = sQs + BPB * 16;         // 64

    const int t  = threadIdx.x;
    const int b0 = blockIdx.x * BPB;

    // Load Wq/Wk with pitch-65 padding (conflict-free column reads later)
    for (int i = t; i < 64 * 64; i += 256) {
        const int e = i >> 6, d = i & 63;
        sWq[e * 65 + d] = Wq[i];
        sWk[e * 65 + d] = Wk[i];
    }
    // Load x, v tiles (vectorized)
    {
        const float4* x4 = (const float4*)(x + (size_t)b0 * 1024);
        const float4* v4 = (const float4*)(v + (size_t)b0 * 1024);
        float4* sX4 = (float4*)sX;
        float4* sV4 = (float4*)sV;
        #pragma unroll
        for (int i = t; i < BPB * 256; i += 256) { sX4[i] = x4[i]; sV4[i] = v4[i]; }
    }
    __syncthreads();

    // q = x @ Wq^T + bq ; k = x @ Wk^T + bk   (store pitch 65, inner index e)
    for (int i = t; i < BPB * 1024; i += 256) {
        const int e  = i & 63;
        const int hh = i >> 6;                 // bb*16 + h
        const float* xr = sX  + hh * 64;
        const float* wq = sWq + e * 65;
        const float* wk = sWk + e * 65;
        float aq = bq[e], ak = bk[e];
        #pragma unroll
        for (int d = 0; d < 64; d++) {
            const float xv = xr[d];
            aq = fmaf(xv, wq[d], aq);
            ak = fmaf(xv, wk[d], ak);
        }
        sQ[hh * 65 + e] = aq;
        sK[hh * 65 + e] = ak;
    }
    __syncthreads();

    // squared norms per (batch, head) row
    if (t < BPB * 16) {
        const float* qr = sQ + t * 65;
        const float* kr = sK + t * 65;
        float sq = 0.f, sk = 0.f;
        #pragma unroll
        for (int e = 0; e < 64; e++) {
            sq = fmaf(qr[e], qr[e], sq);
            sk = fmaf(kr[e], kr[e], sk);
        }
        sQs[t] = sq;
        sKs[t] = sk;
    }
    __syncthreads();

    // -dist[h][g] = -(max(q2 + k2 - 2*q.k, 0))
    for (int i = t; i < BPB * 256; i += 256) {
        const int g  = i & 15;
        const int hh = i >> 4;                 // bb*16 + h
        const int bb = i >> 8;
        const float* qr = sQ + hh * 65;
        const float* kr = sK + (bb * 16 + g) * 65;
        float dot = 0.f;
        #pragma unroll
        for (int e = 0; e < 64; e++) dot = fmaf(qr[e], kr[e], dot);
        float dist = sQs[hh] + sKs[bb * 16 + g] - 2.f * dot;
        dist = fmaxf(dist, 0.f);
        sA[hh * 17 + g] = -dist;
    }
    __syncthreads();

    // softmax over g (row of 16), one thread per (batch, head)
    if (t < BPB * 16) {
        float* r = sA + t * 17;
        float m = r[0];
        #pragma unroll
        for (int g = 1; g < 16; g++) m = fmaxf(m, r[g]);
        float s = 0.f;
        #pragma unroll
        for (int g = 0; g < 16; g++) { const float e = expf(r[g] - m); r[g] = e; s += e; }
        const float inv = 1.f / s;
        #pragma unroll
        for (int g = 0; g < 16; g++) r[g] *= inv;
    }
    __syncthreads();

    // mixed = attn @ {x, v}; rows of g_mixed: [0,B)=x_mixed, [B,2B)=v_mixed
    for (int i = t; i < BPB * 1024; i += 256) {
        const int d  = i & 63;
        const int hh = i >> 6;
        const int bb = i >> 10;
        const float* ar = sA + hh * 17;
        float ax = 0.f, av = 0.f;
        #pragma unroll
        for (int g = 0; g < 16; g++) {
            const float a = ar[g];
            ax = fmaf(a, sX[(bb * 16 + g) * 64 + d], ax);
            av = fmaf(a, sV[(bb * 16 + g) * 64 + d], av);
        }
        const size_t row = (size_t)b0 * 1024 + (size_t)i;  // (b0+bb)*1024 + h*64 + d
        g_mixed[row] = ax;
        g_mixed[(size_t)B * 1024 + row] = av;
    }
}

// ---------------------------------------------------------------------------
// Kernel B: C[r][e] = bo[e] + sum_d mixed[r][d] * Wo[e][d]
// M = 2B = 65536, N = 1024, K = 1024. 128x128x8 tile, 256 threads,
// 8x8 micro-tile with f32x2 packed FMA (pairs along N).
// ---------------------------------------------------------------------------
__global__ __launch_bounds__(256, 2) void out_gemm_kernel(
    const float* __restrict__ W,   // Wo [1024,1024] (N-major rows, K contiguous)
    const float* __restrict__ bo,
    float* __restrict__ C)
{
    __shared__ __align__(16) float As[8][132];
    __shared__ __align__(16) float Bs[8][132];

    const int t   = threadIdx.x;
    const int tx  = t & 15;
    const int ty  = t >> 4;
    const int row = t >> 1;                // 0..127 (tile row for loading)
    const int kq  = (t & 1) * 4;           // 0 or 4

    const float* Ag = g_mixed + (size_t)(blockIdx.y * 128 + row) * 1024 + kq;
    const float* Wg = W       + (size_t)(blockIdx.x * 128 + row) * 1024 + kq;

    u64 acc[8][4];
    #pragma unroll
    for (int i = 0; i < 8; i++)
        #pragma unroll
        for (int j = 0; j < 4; j++) acc[i][j] = 0ull;

    float4 ar = *(const float4*)Ag;
    float4 wr = *(const float4*)Wg;

    for (int kt = 0; kt < 1024; kt += 8) {
        // transposed store into smem (pitch 132 -> conflict-free)
        As[kq + 0][row] = ar.x; As[kq + 1][row] = ar.y;
        As[kq + 2][row] = ar.z; As[kq + 3][row] = ar.w;
        Bs[kq + 0][row] = wr.x; Bs[kq + 1][row] = wr.y;
        Bs[kq + 2][row] = wr.z; Bs[kq + 3][row] = wr.w;
        __syncthreads();

        // prefetch next K-slab (latency hidden under the compute below)
        if (kt + 8 < 1024) {
            ar = *(const float4*)(Ag + kt + 8);
            wr = *(const float4*)(Wg + kt + 8);
        }

        #pragma unroll
        for (int k = 0; k < 8; k++) {
            const float4 a0 = *(const float4*)&As[k][ty * 4];
            const float4 a1 = *(const float4*)&As[k][64 + ty * 4];
            const u64 b0 = *(const u64*)&Bs[k][tx * 4];
            const u64 b1 = *(const u64*)&Bs[k][tx * 4 + 2];
            const u64 b2 = *(const u64*)&Bs[k][64 + tx * 4];
            const u64 b3 = *(const u64*)&Bs[k][64 + tx * 4 + 2];
            u64 a2[8];
            a2[0] = pack2(a0.x, a0.x); a2[1] = pack2(a0.y, a0.y);
            a2[2] = pack2(a0.z, a0.z); a2[3] = pack2(a0.w, a0.w);
            a2[4] = pack2(a1.x, a1.x); a2[5] = pack2(a1.y, a1.y);
            a2[6] = pack2(a1.z, a1.z); a2[7] = pack2(a1.w, a1.w);
            #pragma unroll
            for (int i = 0; i < 8; i++) {
                fma2(acc[i][0], a2[i], b0);
                fma2(acc[i][1], a2[i], b1);
                fma2(acc[i][2], a2[i], b2);
                fma2(acc[i][3], a2[i], b3);
            }
        }
        __syncthreads();
    }

    // epilogue: + bias, write to d_out (rows map 1:1 to out_x || out_v)
    const int n0 = blockIdx.x * 128;
    float bias[8];
    #pragma unroll
    for (int j = 0; j < 4; j++) {
        bias[j]     = bo[n0 + tx * 4 + j];
        bias[4 + j] = bo[n0 + 64 + tx * 4 + j];
    }
    const size_t m0 = (size_t)blockIdx.y * 128;
    #pragma unroll
    for (int i = 0; i < 8; i++) {
        const int m = (i < 4) ? (ty * 4 + i) : (64 + ty * 4 + (i - 4));
        float* out = C + (m0 + m) * 1024 + n0;
        const float2 c0 = unpack2(acc[i][0]);
        const float2 c1 = unpack2(acc[i][1]);
        const float2 c2 = unpack2(acc[i][2]);
        const float2 c3 = unpack2(acc[i][3]);
        const float4 lo = make_float4(c0.x + bias[0], c0.y + bias[1],
                                      c1.x + bias[2], c1.y + bias[3]);
        const float4 hi = make_float4(c2.x + bias[4], c2.y + bias[5],
                                      c3.x + bias[6], c3.y + bias[7]);
        *(float4*)(out + tx * 4)      = lo;
        *(float4*)(out + 64 + tx * 4) = hi;
    }
}

extern "C" void kernel_launch(void* const* d_in, const int* in_sizes, int n_in,
                              void* d_out, int out_size)
{
    const float* x  = (const float*)d_in[0];
    const float* v  = (const float*)d_in[1];
    const float* Wq = (const float*)d_in[2];
    const float* bq = (const float*)d_in[3];
    const float* Wk = (const float*)d_in[4];
    const float* bk = (const float*)d_in[5];
    const float* Wo = (const float*)d_in[6];
    const float* bo = (const float*)d_in[7];
    float* out = (float*)d_out;

    const int B = in_sizes[0] / 1024;   // 32768

    // dynamic smem for the attention kernel: 26048 floats = 104192 bytes
    const int smem_bytes = (64 * 65 * 2 + BPB * 1024 * 2 + BPB * 16 * 65 * 2 +
                            BPB * 16 * 17 + BPB * 16 * 2) * (int)sizeof(float);
    cudaFuncSetAttribute(attn_mix_kernel,
                         cudaFuncAttributeMaxDynamicSharedMemorySize, smem_bytes);

    attn_mix_kernel<<<B / BPB, 256, smem_bytes>>>(x, v, Wq, bq, Wk, bk, B);

    dim3 grid(1024 / 128, (2 * B) / 128);  // (8, 512)
    out_gemm_kernel<<<grid, 256>>>(Wo, bo, out);
}

// round 11
// speedup vs baseline: 1.7887x; 1.7887x over previous
#include <cuda_runtime.h>
#include <cuda_bf16.h>
#include <cstdint>

// ===========================================================================
// Scratch (no allocations allowed): bf16 3-term concat operands.
// g_A: [2B=65536 rows, 3072]  = [Ahi | Ahi | Alo]   (384 MiB)
// g_B: [1024 rows,   3072]    = [Whi | Wlo | Whi]   (6 MiB)
// ===========================================================================
__device__ __align__(16) __nv_bfloat16 g_A[(size_t)65536 * 3072];
__device__ __align__(16) __nv_bfloat16 g_B[(size_t)1024 * 3072];

// ---------------------------------------------------------------------------
// PTX helpers — ONLY non-arch-suffixed instructions (target is plain sm_103):
// cp.async (sm_80), ldmatrix (sm_75), mma.sync bf16 (sm_80).
// ---------------------------------------------------------------------------
__device__ __forceinline__ uint32_t smem_u32(const void* p) {
    uint32_t a;
    asm("{ .reg .u64 t; cvta.to.shared.u64 t, %1; cvt.u32.u64 %0, t; }"
        : "=r"(a) : "l"(p));
    return a;
}
__device__ __forceinline__ void cp_async16(uint32_t s, const void* g) {
    asm volatile("cp.async.cg.shared.global [%0], [%1], 16;" :: "r"(s), "l"(g) : "memory");
}
#define CP_COMMIT() asm volatile("cp.async.commit_group;" ::: "memory")
#define CP_WAIT1()  asm volatile("cp.async.wait_group 1;" ::: "memory")

__device__ __forceinline__ void ldm4(uint32_t* r, uint32_t addr) {
    asm volatile("ldmatrix.sync.aligned.m8n8.x4.shared.b16 {%0,%1,%2,%3}, [%4];"
                 : "=r"(r[0]), "=r"(r[1]), "=r"(r[2]), "=r"(r[3]) : "r"(addr));
}
__device__ __forceinline__ void mma16816(float* c, const uint32_t* a,
                                         uint32_t b0, uint32_t b1) {
    asm volatile(
        "mma.sync.aligned.m16n8k16.row.col.f32.bf16.bf16.f32 "
        "{%0,%1,%2,%3}, {%4,%5,%6,%7}, {%8,%9}, {%0,%1,%2,%3};"
        : "+f"(c[0]), "+f"(c[1]), "+f"(c[2]), "+f"(c[3])
        : "r"(a[0]), "r"(a[1]), "r"(a[2]), "r"(a[3]), "r"(b0), "r"(b1));
}

#define BPB 4  // batches per block in the attention kernel

// ===========================================================================
// Kernel A: q/k projection + geodesic softmax + mixing, 4 batches per block.
// Writes x_mixed/v_mixed directly as bf16 hi/hi/lo planes into g_A.
// ===========================================================================
__global__ __launch_bounds__(256) void attn_mix_kernel(
    const float* __restrict__ x, const float* __restrict__ v,
    const float* __restrict__ Wq, const float* __restrict__ bq,
    const float* __restrict__ Wk, const float* __restrict__ bk,
    int B)
{
    extern __shared__ float sm[];
    float* sWq = sm;                     // 4160
    float* sWk = sWq + 64 * 65;          // 4160
    float* sX  = sWk + 64 * 65;          // 4096
    float* sV  = sX  + BPB * 1024;       // 4096
    float* sQ  = sV  + BPB * 1024;       // 4160
    float* sK  = sQ  + BPB * 16 * 65;    // 4160
    float* sA  = sK  + BPB * 16 * 65;    // 1088
    float* sQs = sA  + BPB * 16 * 17;    // 64
    float* sKs = sQs + BPB * 16;         // 64

    const int t  = threadIdx.x;
    const int b0 = blockIdx.x * BPB;

    for (int i = t; i < 64 * 64; i += 256) {
        const int e = i >> 6, d = i & 63;
        sWq[e * 65 + d] = Wq[i];
        sWk[e * 65 + d] = Wk[i];
    }
    {
        const float4* x4 = (const float4*)(x + (size_t)b0 * 1024);
        const float4* v4 = (const float4*)(v + (size_t)b0 * 1024);
        float4* sX4 = (float4*)sX;
        float4* sV4 = (float4*)sV;
        #pragma unroll
        for (int i = t; i < BPB * 256; i += 256) { sX4[i] = x4[i]; sV4[i] = v4[i]; }
    }
    __syncthreads();

    // q = x @ Wq^T + bq ; k = x @ Wk^T + bk
    for (int i = t; i < BPB * 1024; i += 256) {
        const int e  = i & 63;
        const int hh = i >> 6;
        const float* xr = sX  + hh * 64;
        const float* wq = sWq + e * 65;
        const float* wk = sWk + e * 65;
        float aq = bq[e], ak = bk[e];
        #pragma unroll
        for (int d = 0; d < 64; d++) {
            const float xv = xr[d];
            aq = fmaf(xv, wq[d], aq);
            ak = fmaf(xv, wk[d], ak);
        }
        sQ[hh * 65 + e] = aq;
        sK[hh * 65 + e] = ak;
    }
    __syncthreads();

    if (t < BPB * 16) {
        const float* qr = sQ + t * 65;
        const float* kr = sK + t * 65;
        float sq = 0.f, sk = 0.f;
        #pragma unroll
        for (int e = 0; e < 64; e++) {
            sq = fmaf(qr[e], qr[e], sq);
            sk = fmaf(kr[e], kr[e], sk);
        }
        sQs[t] = sq;
        sKs[t] = sk;
    }
    __syncthreads();

    for (int i = t; i < BPB * 256; i += 256) {
        const int g  = i & 15;
        const int hh = i >> 4;
        const int bb = i >> 8;
        const float* qr = sQ + hh * 65;
        const float* kr = sK + (bb * 16 + g) * 65;
        float dot = 0.f;
        #pragma unroll
        for (int e = 0; e < 64; e++) dot = fmaf(qr[e], kr[e], dot);
        float dist = sQs[hh] + sKs[bb * 16 + g] - 2.f * dot;
        dist = fmaxf(dist, 0.f);
        sA[hh * 17 + g] = -dist;
    }
    __syncthreads();

    if (t < BPB * 16) {
        float* r = sA + t * 17;
        float m = r[0];
        #pragma unroll
        for (int g = 1; g < 16; g++) m = fmaxf(m, r[g]);
        float s = 0.f;
        #pragma unroll
        for (int g = 0; g < 16; g++) { const float e = expf(r[g] - m); r[g] = e; s += e; }
        const float inv = 1.f / s;
        #pragma unroll
        for (int g = 0; g < 16; g++) r[g] *= inv;
    }
    __syncthreads();

    // mixed = attn @ {x, v}; split to bf16 hi/lo and write planes [hi|hi|lo]
    for (int i = t; i < BPB * 1024; i += 256) {
        const int d  = i & 63;
        const int hh = i >> 6;
        const int bb = i >> 10;
        const float* ar = sA + hh * 17;
        float ax = 0.f, av = 0.f;
        #pragma unroll
        for (int g = 0; g < 16; g++) {
            const float a = ar[g];
            ax = fmaf(a, sX[(bb * 16 + g) * 64 + d], ax);
            av = fmaf(a, sV[(bb * 16 + g) * 64 + d], av);
        }
        const int col = i & 1023;
        const size_t rowx = (size_t)(b0 + bb) * 3072;
        const size_t rowv = (size_t)(B + b0 + bb) * 3072;
        const __nv_bfloat16 hx = __float2bfloat16(ax);
        const __nv_bfloat16 lx = __float2bfloat16(ax - __bfloat162float(hx));
        const __nv_bfloat16 hv = __float2bfloat16(av);
        const __nv_bfloat16 lv = __float2bfloat16(av - __bfloat162float(hv));
        g_A[rowx + col] = hx; g_A[rowx + 1024 + col] = hx; g_A[rowx + 2048 + col] = lx;
        g_A[rowv + col] = hv; g_A[rowv + 1024 + col] = hv; g_A[rowv + 2048 + col] = lv;
    }
}

// ===========================================================================
// Kernel W: convert Wo [1024,1024] fp32 -> g_B planes [Whi | Wlo | Whi]
// ===========================================================================
__global__ __launch_bounds__(256) void conv_wo_kernel(const float* __restrict__ Wo)
{
    const int i = blockIdx.x * 256 + threadIdx.x;   // 0 .. 1M-1
    const int e = i >> 10, k = i & 1023;
    const float w = Wo[i];
    const __nv_bfloat16 h = __float2bfloat16(w);
    const __nv_bfloat16 l = __float2bfloat16(w - __bfloat162float(h));
    const size_t r = (size_t)e * 3072;
    g_B[r + k] = h;
    g_B[r + 1024 + k] = l;
    g_B[r + 2048 + k] = h;
}

// ===========================================================================
// Kernel B: warp-level HMMA bf16 GEMM (mma.sync m16n8k16, fp32 accum).
// C[m][n] = bo[n] + sum_k g_A[m][k] * g_B[n][k].  M=65536, N=1024, K=3072.
// CTA tile 128x128, K-chunk 64 (one 128B smem row per tile row),
// 3-stage cp.async pipeline, XOR-16B swizzle (conflict-free ldmatrix).
// ===========================================================================
#define KTOT    3072
#define G_KC    64
#define NCH     (KTOT / G_KC)       // 48
#define STAGE_B 32768               // A tile 16KB + B tile 16KB
#define GSMEM   (3 * STAGE_B)       // 98304

__device__ __forceinline__ void load_stage(
    const __nv_bfloat16* Ag, const __nv_bfloat16* Bg,
    uint32_t sbase, int c, int tid)
{
    const uint32_t sa = sbase + (uint32_t)(c % 3) * STAGE_B;
    const uint32_t sb = sa + 16384u;
    const int kb = c * G_KC;
    #pragma unroll
    for (int i = 0; i < 4; i++) {
        const int ch = tid + i * 256;
        const int row = ch >> 3, cc = ch & 7;
        cp_async16(sa + row * 128 + ((cc ^ (row & 7)) << 4),
                   Ag + (size_t)row * KTOT + kb + cc * 8);
    }
    #pragma unroll
    for (int i = 0; i < 4; i++) {
        const int ch = tid + i * 256;
        const int row = ch >> 3, cc = ch & 7;
        cp_async16(sb + row * 128 + ((cc ^ (row & 7)) << 4),
                   Bg + (size_t)row * KTOT + kb + cc * 8);
    }
    CP_COMMIT();
}

__global__ void __launch_bounds__(256) out_gemm_mma(
    const float* __restrict__ bo, float* __restrict__ C)
{
    extern __shared__ char smem[];
    const uint32_t sbase = smem_u32(smem);
    const int tid = threadIdx.x;
    const int lid = tid & 31;
    const int wid = tid >> 5;
    const int mw  = wid >> 1;          // 0..3  (m subtile of 32)
    const int nw  = wid & 1;           // 0..1  (n subtile of 64)
    const int m0  = blockIdx.y * 128;
    const int n0  = blockIdx.x * 128;

    const __nv_bfloat16* Ag = g_A + (size_t)m0 * KTOT;
    const __nv_bfloat16* Bg = g_B + (size_t)n0 * KTOT;

    float acc[2][8][4];
    #pragma unroll
    for (int i = 0; i < 2; i++)
        #pragma unroll
        for (int j = 0; j < 8; j++)
            #pragma unroll
            for (int q = 0; q < 4; q++) acc[i][j][q] = 0.f;

    load_stage(Ag, Bg, sbase, 0, tid);
    load_stage(Ag, Bg, sbase, 1, tid);

    const int lane15 = lid & 15;
    const int laneHi = lid >> 4;       // 0/1 -> +8 k elements (one 16B chunk)

    for (int c = 0; c < NCH; c++) {
        CP_WAIT1();                    // stage c resident (c+1 may be in flight)
        __syncthreads();
        if (c + 2 < NCH) load_stage(Ag, Bg, sbase, c + 2, tid);
        else             CP_COMMIT();  // empty group keeps the count uniform

        const uint32_t sa = sbase + (uint32_t)(c % 3) * STAGE_B;
        const uint32_t sb = sa + 16384u;

        #pragma unroll
        for (int kk = 0; kk < 4; kk++) {
            const int kc = kk * 2 + laneHi;    // 16B-chunk index within row
            uint32_t a[2][4];
            #pragma unroll
            for (int bm = 0; bm < 2; bm++) {
                const int row = mw * 32 + bm * 16 + lane15;
                ldm4(a[bm], sa + row * 128 + ((kc ^ (row & 7)) << 4));
            }
            #pragma unroll
            for (int bn = 0; bn < 4; bn++) {
                uint32_t b[4];
                const int row = nw * 64 + bn * 16 + lane15;
                ldm4(b, sb + row * 128 + ((kc ^ (row & 7)) << 4));
                #pragma unroll
                for (int bm = 0; bm < 2; bm++) {
                    mma16816(acc[bm][2 * bn],     a[bm], b[0], b[2]);
                    mma16816(acc[bm][2 * bn + 1], a[bm], b[1], b[3]);
                }
            }
        }
    }

    // epilogue: + bias, fp32 stores
    const int r4 = lid >> 2;
    const int c2 = (lid & 3) * 2;
    #pragma unroll
    for (int bm = 0; bm < 2; bm++) {
        const int row = m0 + mw * 32 + bm * 16 + r4;
        #pragma unroll
        for (int bn8 = 0; bn8 < 8; bn8++) {
            const int col = n0 + nw * 64 + bn8 * 8 + c2;
            const float bb0 = bo[col], bb1 = bo[col + 1];
            float* p0 = C + (size_t)row * 1024 + col;
            float* p1 = p0 + 8 * 1024;
            *(float2*)p0 = make_float2(acc[bm][bn8][0] + bb0, acc[bm][bn8][1] + bb1);
            *(float2*)p1 = make_float2(acc[bm][bn8][2] + bb0, acc[bm][bn8][3] + bb1);
        }
    }
}

// ===========================================================================
extern "C" void kernel_launch(void* const* d_in, const int* in_sizes, int n_in,
                              void* d_out, int out_size)
{
    const float* x  = (const float*)d_in[0];
    const float* v  = (const float*)d_in[1];
    const float* Wq = (const float*)d_in[2];
    const float* bq = (const float*)d_in[3];
    const float* Wk = (const float*)d_in[4];
    const float* bk = (const float*)d_in[5];
    const float* Wo = (const float*)d_in[6];
    const float* bo = (const float*)d_in[7];
    float* out = (float*)d_out;

    const int B = in_sizes[0] / 1024;   // 32768

    const int attn_smem = (64 * 65 * 2 + BPB * 1024 * 2 + BPB * 16 * 65 * 2 +
                           BPB * 16 * 17 + BPB * 16 * 2) * (int)sizeof(float);
    cudaFuncSetAttribute(attn_mix_kernel,
                         cudaFuncAttributeMaxDynamicSharedMemorySize, attn_smem);
    cudaFuncSetAttribute(out_gemm_mma,
                         cudaFuncAttributeMaxDynamicSharedMemorySize, GSMEM);

    attn_mix_kernel<<<B / BPB, 256, attn_smem>>>(x, v, Wq, bq, Wk, bk, B);
    conv_wo_kernel<<<4096, 256>>>(Wo);

    dim3 grid(1024 / 128, (2 * B) / 128);   // (8, 512) — x fastest => A reuse in L2
    out_gemm_mma<<<grid, 256, GSMEM>>>(bo, out);
}